// round 10
// baseline (speedup 1.0000x reference)
#include <cuda_runtime.h>
#include <math.h>
#include <stdint.h>

#define D_MODEL 512
#define NHEAD   8
#define D_HEAD  64
#define BATCH   2
#define LQ      2048
#define LK      4096

// Scratch (static device globals — allocation-free)
__device__ float g_Qp [BATCH * LQ * D_MODEL];   // 8 MB
__device__ float g_Kp [BATCH * LK * D_MODEL];   // 16 MB
__device__ float g_Vp [BATCH * LK * D_MODEL];   // 16 MB
__device__ float g_Att[BATCH * LQ * D_MODEL];   // 8 MB

// ---------------------------------------------------------------------------
// tf32 helpers
// ---------------------------------------------------------------------------
__device__ __forceinline__ uint32_t f2tf32(float f) {
    uint32_t r;
    asm("cvt.rna.tf32.f32 %0, %1;" : "=r"(r) : "f"(f));
    return r;
}
__device__ __forceinline__ float f2tf32f(float f) {
    return __uint_as_float(f2tf32(f));
}

// D += A(16x8,row) * B(8x8,col), tf32 in, fp32 acc
__device__ __forceinline__ void mma_tf32(float* d, const uint32_t* a,
                                         uint32_t b0, uint32_t b1) {
    asm volatile(
        "mma.sync.aligned.m16n8k8.row.col.f32.tf32.tf32.f32 "
        "{%0,%1,%2,%3},{%4,%5,%6,%7},{%8,%9},{%0,%1,%2,%3};"
        : "+f"(d[0]), "+f"(d[1]), "+f"(d[2]), "+f"(d[3])
        : "r"(a[0]), "r"(a[1]), "r"(a[2]), "r"(a[3]), "r"(b0), "r"(b1));
}

// ---------------------------------------------------------------------------
// GEMM: Y[M,512] = X[M,512] @ W[512,512]^T + bias (W row-major [out,in]).
// Tensor-core tf32. CTA tile 128x64, BK=32, 256 threads = 8 warps (4x2).
// Smem pad 36 (stride mod 32 == 4) => fragment LDS is conflict-free.
// ---------------------------------------------------------------------------
__global__ __launch_bounds__(256) void gemm_tc_kernel(
    const float* __restrict__ X, const float* __restrict__ W,
    const float* __restrict__ bias, float* __restrict__ Y)
{
    __shared__ float Xs[128][36];
    __shared__ float Ws[64][36];

    const int t      = threadIdx.x;
    const int lane   = t & 31;
    const int w      = t >> 5;
    const int warp_m = w >> 1;          // 0..3 -> 32 rows each
    const int warp_n = w & 1;           // 0..1 -> 32 cols each
    const int grp    = lane >> 2;       // 0..7
    const int tig    = lane & 3;        // 0..3
    const int m0     = blockIdx.y * 128;
    const int n0     = blockIdx.x * 64;

    float acc[2][4][4] = {};            // [mtile][ntile][frag]

    for (int k0 = 0; k0 < D_MODEL; k0 += 32) {
        // Fill Xs (128x32) and Ws (64x32), converting to tf32.
        #pragma unroll
        for (int rep = 0; rep < 4; rep++) {
            int idx = t + rep * 256;    // 0..1023
            int r = idx >> 3, c = idx & 7;
            float4 v = *(const float4*)(X + (size_t)(m0 + r) * D_MODEL + k0 + 4 * c);
            float4 o;
            o.x = f2tf32f(v.x); o.y = f2tf32f(v.y);
            o.z = f2tf32f(v.z); o.w = f2tf32f(v.w);
            *(float4*)&Xs[r][4 * c] = o;
        }
        #pragma unroll
        for (int rep = 0; rep < 2; rep++) {
            int idx = t + rep * 256;    // 0..511
            int r = idx >> 3, c = idx & 7;
            float4 v = *(const float4*)(W + (size_t)(n0 + r) * D_MODEL + k0 + 4 * c);
            float4 o;
            o.x = f2tf32f(v.x); o.y = f2tf32f(v.y);
            o.z = f2tf32f(v.z); o.w = f2tf32f(v.w);
            *(float4*)&Ws[r][4 * c] = o;
        }
        __syncthreads();

        #pragma unroll
        for (int ks = 0; ks < 4; ks++) {
            const int kk = ks * 8;
            uint32_t af[2][4];
            #pragma unroll
            for (int mt = 0; mt < 2; mt++) {
                int r = warp_m * 32 + mt * 16 + grp;
                af[mt][0] = __float_as_uint(Xs[r][kk + tig]);
                af[mt][1] = __float_as_uint(Xs[r + 8][kk + tig]);
                af[mt][2] = __float_as_uint(Xs[r][kk + tig + 4]);
                af[mt][3] = __float_as_uint(Xs[r + 8][kk + tig + 4]);
            }
            #pragma unroll
            for (int nt = 0; nt < 4; nt++) {
                int n = warp_n * 32 + nt * 8 + grp;
                uint32_t b0 = __float_as_uint(Ws[n][kk + tig]);
                uint32_t b1 = __float_as_uint(Ws[n][kk + tig + 4]);
                #pragma unroll
                for (int mt = 0; mt < 2; mt++)
                    mma_tf32(acc[mt][nt], af[mt], b0, b1);
            }
        }
        __syncthreads();
    }

    // Epilogue: + bias, write fp32
    #pragma unroll
    for (int mt = 0; mt < 2; mt++) {
        int r = m0 + warp_m * 32 + mt * 16 + grp;
        #pragma unroll
        for (int nt = 0; nt < 4; nt++) {
            int c = n0 + warp_n * 32 + nt * 8 + tig * 2;
            float b0 = bias[c], b1 = bias[c + 1];
            Y[(size_t)r * D_MODEL + c]           = acc[mt][nt][0] + b0;
            Y[(size_t)r * D_MODEL + c + 1]       = acc[mt][nt][1] + b1;
            Y[(size_t)(r + 8) * D_MODEL + c]     = acc[mt][nt][2] + b0;
            Y[(size_t)(r + 8) * D_MODEL + c + 1] = acc[mt][nt][3] + b1;
        }
    }
}

// ---------------------------------------------------------------------------
// Flash attention (tensor core). CTA = (b, h, 64-q-row tile). 256 thr, 8 warps.
// Warp tile: 16 q-rows (warp_m=w>>1) x 32 cols (warp_n=w&1).
// Q fragments in registers; K row-major and V transposed in smem (both are
// the `col` B operand). Parallel online softmax: 4 threads per row.
// ---------------------------------------------------------------------------
struct AttnSmem {
    float Ks[64][68];   // [kpos][d]   (tf32 bits)
    float Vt[64][68];   // [d][kpos]   (tf32 bits)
    float Ss[64][68];   // scores, then probabilities (tf32 bits)
    float gb[64];
    float mrow[64];
    float lrow[64];
    float cfac[64];
};
extern __shared__ unsigned char attn_smem_raw[];

__global__ __launch_bounds__(256) void attn_tc_kernel(
    const float* __restrict__ key_gate, const int* __restrict__ key_mask)
{
    AttnSmem& s = *reinterpret_cast<AttnSmem*>(attn_smem_raw);

    const int t      = threadIdx.x;
    const int lane   = t & 31;
    const int w      = t >> 5;
    const int warp_m = w >> 1;          // 0..3
    const int warp_n = w & 1;           // 0..1
    const int grp    = lane >> 2;
    const int tig    = lane & 3;
    const int q0     = blockIdx.x * 64;
    const int h      = blockIdx.y;
    const int b      = blockIdx.z;

    // --- Q fragments in registers (rows warp_m*16 .. +15, k = 0..63) ---
    const float* Qb = g_Qp + ((size_t)b * LQ + q0) * D_MODEL + h * D_HEAD;
    uint32_t qf[8][4];
    {
        const int r0 = warp_m * 16 + grp;
        #pragma unroll
        for (int ks = 0; ks < 8; ks++) {
            int kb = ks * 8;
            qf[ks][0] = f2tf32(Qb[(size_t)r0 * D_MODEL + kb + tig]);
            qf[ks][1] = f2tf32(Qb[(size_t)(r0 + 8) * D_MODEL + kb + tig]);
            qf[ks][2] = f2tf32(Qb[(size_t)r0 * D_MODEL + kb + tig + 4]);
            qf[ks][3] = f2tf32(Qb[(size_t)(r0 + 8) * D_MODEL + kb + tig + 4]);
        }
    }
    if (t < 64) { s.mrow[t] = -1e30f; s.lrow[t] = 0.0f; }

    float oacc[4][4] = {};
    const float scale = 0.125f;   // 1/sqrt(64)
    const int row  = t >> 2;      // softmax mapping: 4 threads / row
    const int part = t & 3;

    __syncthreads();

    for (int kt = 0; kt < LK / 64; kt++) {
        const int k0 = kt * 64;
        const float* Kb = g_Kp + ((size_t)b * LK + k0) * D_MODEL + h * D_HEAD;
        const float* Vb = g_Vp + ((size_t)b * LK + k0) * D_MODEL + h * D_HEAD;

        // Load K (row-major) and V (transposed), converting to tf32.
        #pragma unroll
        for (int rep = 0; rep < 4; rep++) {
            int idx = t + rep * 256;    // 0..1023
            int r = idx >> 4, c = idx & 15;
            float4 kv = *(const float4*)(Kb + (size_t)r * D_MODEL + 4 * c);
            float4 o;
            o.x = f2tf32f(kv.x); o.y = f2tf32f(kv.y);
            o.z = f2tf32f(kv.z); o.w = f2tf32f(kv.w);
            *(float4*)&s.Ks[r][4 * c] = o;
            float4 vv = *(const float4*)(Vb + (size_t)r * D_MODEL + 4 * c);
            s.Vt[4 * c + 0][r] = f2tf32f(vv.x);
            s.Vt[4 * c + 1][r] = f2tf32f(vv.y);
            s.Vt[4 * c + 2][r] = f2tf32f(vv.z);
            s.Vt[4 * c + 3][r] = f2tf32f(vv.w);
        }
        if (t < 64) {
            int k = k0 + t;
            float g = key_gate[(size_t)b * LK + k];
            s.gb[t] = (key_mask[(size_t)b * LK + k] == 0)
                          ? -1e30f : logf(fmaxf(g, 1e-6f));
        }
        __syncthreads();

        // ---- S = Q @ K^T (scaled) ----
        {
            float sacc[4][4] = {};
            #pragma unroll
            for (int ks = 0; ks < 8; ks++) {
                const int kk = ks * 8;
                #pragma unroll
                for (int nt = 0; nt < 4; nt++) {
                    int n = warp_n * 32 + nt * 8 + grp;
                    uint32_t b0 = __float_as_uint(s.Ks[n][kk + tig]);
                    uint32_t b1 = __float_as_uint(s.Ks[n][kk + tig + 4]);
                    mma_tf32(sacc[nt], qf[ks], b0, b1);
                }
            }
            const int r = warp_m * 16 + grp;
            #pragma unroll
            for (int nt = 0; nt < 4; nt++) {
                int c = warp_n * 32 + nt * 8 + tig * 2;
                s.Ss[r][c]         = sacc[nt][0] * scale;
                s.Ss[r][c + 1]     = sacc[nt][1] * scale;
                s.Ss[r + 8][c]     = sacc[nt][2] * scale;
                s.Ss[r + 8][c + 1] = sacc[nt][3] * scale;
            }
        }
        __syncthreads();

        // ---- online softmax: 4 threads per row, 16 cols each ----
        {
            float v[16];
            float mloc = -1e30f;
            #pragma unroll
            for (int i = 0; i < 4; i++) {
                float4 sv = *(float4*)&s.Ss[row][part * 16 + 4 * i];
                float4 gv = *(float4*)&s.gb[part * 16 + 4 * i];
                v[4*i+0] = sv.x + gv.x; v[4*i+1] = sv.y + gv.y;
                v[4*i+2] = sv.z + gv.z; v[4*i+3] = sv.w + gv.w;
                mloc = fmaxf(mloc, fmaxf(fmaxf(v[4*i], v[4*i+1]),
                                         fmaxf(v[4*i+2], v[4*i+3])));
            }
            mloc = fmaxf(mloc, __shfl_xor_sync(0xffffffff, mloc, 1));
            mloc = fmaxf(mloc, __shfl_xor_sync(0xffffffff, mloc, 2));
            float m_old = s.mrow[row];
            float m_new = fmaxf(m_old, mloc);

            float sum = 0.0f;
            #pragma unroll
            for (int i = 0; i < 4; i++) {
                float4 pv;
                float p0 = __expf(v[4*i+0] - m_new);
                float p1 = __expf(v[4*i+1] - m_new);
                float p2 = __expf(v[4*i+2] - m_new);
                float p3 = __expf(v[4*i+3] - m_new);
                sum += (p0 + p1) + (p2 + p3);
                pv.x = f2tf32f(p0); pv.y = f2tf32f(p1);
                pv.z = f2tf32f(p2); pv.w = f2tf32f(p3);
                *(float4*)&s.Ss[row][part * 16 + 4 * i] = pv;
            }
            sum += __shfl_xor_sync(0xffffffff, sum, 1);
            sum += __shfl_xor_sync(0xffffffff, sum, 2);
            if (part == 0) {
                float cf = __expf(m_old - m_new);
                s.cfac[row] = cf;
                s.lrow[row] = s.lrow[row] * cf + sum;
                s.mrow[row] = m_new;
            }
        }
        __syncthreads();

        // ---- O = O*cfac + P @ V ----
        {
            const int r = warp_m * 16 + grp;
            float cf0 = s.cfac[r], cf1 = s.cfac[r + 8];
            #pragma unroll
            for (int nt = 0; nt < 4; nt++) {
                oacc[nt][0] *= cf0; oacc[nt][1] *= cf0;
                oacc[nt][2] *= cf1; oacc[nt][3] *= cf1;
            }
            #pragma unroll
            for (int ks = 0; ks < 8; ks++) {
                const int kk = ks * 8;
                uint32_t af[4];
                af[0] = __float_as_uint(s.Ss[r][kk + tig]);
                af[1] = __float_as_uint(s.Ss[r + 8][kk + tig]);
                af[2] = __float_as_uint(s.Ss[r][kk + tig + 4]);
                af[3] = __float_as_uint(s.Ss[r + 8][kk + tig + 4]);
                #pragma unroll
                for (int nt = 0; nt < 4; nt++) {
                    int n = warp_n * 32 + nt * 8 + grp;
                    uint32_t b0 = __float_as_uint(s.Vt[n][kk + tig]);
                    uint32_t b1 = __float_as_uint(s.Vt[n][kk + tig + 4]);
                    mma_tf32(oacc[nt], af, b0, b1);
                }
            }
        }
        __syncthreads();
    }

    // ---- normalize + write ----
    {
        const int r = warp_m * 16 + grp;
        float l0 = 1.0f / s.lrow[r], l1 = 1.0f / s.lrow[r + 8];
        float* Ob = g_Att + ((size_t)b * LQ + q0) * D_MODEL + h * D_HEAD;
        #pragma unroll
        for (int nt = 0; nt < 4; nt++) {
            int c = warp_n * 32 + nt * 8 + tig * 2;
            Ob[(size_t)r * D_MODEL + c]           = oacc[nt][0] * l0;
            Ob[(size_t)r * D_MODEL + c + 1]       = oacc[nt][1] * l0;
            Ob[(size_t)(r + 8) * D_MODEL + c]     = oacc[nt][2] * l1;
            Ob[(size_t)(r + 8) * D_MODEL + c + 1] = oacc[nt][3] * l1;
        }
    }
}

// ---------------------------------------------------------------------------
// kernel_launch
// inputs: 0=q 1=kv 2=key_gate 3=key_mask 4=Wq 5=bq 6=Wk 7=bk 8=Wv 9=bv 10=Wo 11=bo
// ---------------------------------------------------------------------------
extern "C" void kernel_launch(void* const* d_in, const int* in_sizes, int n_in,
                              void* d_out, int out_size)
{
    (void)in_sizes; (void)n_in; (void)out_size;

    const float* q        = (const float*)d_in[0];
    const float* kv       = (const float*)d_in[1];
    const float* key_gate = (const float*)d_in[2];
    const int*   key_mask = (const int*)  d_in[3];
    const float* Wq = (const float*)d_in[4];
    const float* bq = (const float*)d_in[5];
    const float* Wk = (const float*)d_in[6];
    const float* bk = (const float*)d_in[7];
    const float* Wv = (const float*)d_in[8];
    const float* bv = (const float*)d_in[9];
    const float* Wo = (const float*)d_in[10];
    const float* bo = (const float*)d_in[11];
    float* out = (float*)d_out;

    float *pQp, *pKp, *pVp, *pAtt;
    cudaGetSymbolAddress((void**)&pQp,  g_Qp);
    cudaGetSymbolAddress((void**)&pKp,  g_Kp);
    cudaGetSymbolAddress((void**)&pVp,  g_Vp);
    cudaGetSymbolAddress((void**)&pAtt, g_Att);

    cudaFuncSetAttribute(attn_tc_kernel,
                         cudaFuncAttributeMaxDynamicSharedMemorySize,
                         (int)sizeof(AttnSmem));

    dim3 blk(256);
    // projections
    gemm_tc_kernel<<<dim3(8, (BATCH * LQ) / 128), blk>>>(q,  Wq, bq, pQp);
    gemm_tc_kernel<<<dim3(8, (BATCH * LK) / 128), blk>>>(kv, Wk, bk, pKp);
    gemm_tc_kernel<<<dim3(8, (BATCH * LK) / 128), blk>>>(kv, Wv, bv, pVp);
    // attention
    attn_tc_kernel<<<dim3(LQ / 64, NHEAD, BATCH), blk, sizeof(AttnSmem)>>>(
        key_gate, key_mask);
    // output projection
    gemm_tc_kernel<<<dim3(8, (BATCH * LQ) / 128), blk>>>(pAtt, Wo, bo, out);
}

// round 11
// speedup vs baseline: 1.0025x; 1.0025x over previous
#include <cuda_runtime.h>
#include <math.h>
#include <stdint.h>

#define D_MODEL 512
#define NHEAD   8
#define D_HEAD  64
#define BATCH   2
#define LQ      2048
#define LK      4096

// Scratch (static device globals — allocation-free)
__device__ float g_Qp [BATCH * LQ * D_MODEL];   // 8 MB
__device__ float g_Kp [BATCH * LK * D_MODEL];   // 16 MB
__device__ float g_Vp [BATCH * LK * D_MODEL];   // 16 MB
__device__ float g_Att[BATCH * LQ * D_MODEL];   // 8 MB

// ---------------------------------------------------------------------------
// tf32 helpers
// ---------------------------------------------------------------------------
__device__ __forceinline__ uint32_t f2tf32(float f) {
    uint32_t r;
    asm("cvt.rna.tf32.f32 %0, %1;" : "=r"(r) : "f"(f));
    return r;
}
__device__ __forceinline__ float f2tf32f(float f) {
    return __uint_as_float(f2tf32(f));
}

// D += A(16x8,row) * B(8x8,col), tf32 in, fp32 acc
__device__ __forceinline__ void mma_tf32(float* d, const uint32_t* a,
                                         uint32_t b0, uint32_t b1) {
    asm volatile(
        "mma.sync.aligned.m16n8k8.row.col.f32.tf32.tf32.f32 "
        "{%0,%1,%2,%3},{%4,%5,%6,%7},{%8,%9},{%0,%1,%2,%3};"
        : "+f"(d[0]), "+f"(d[1]), "+f"(d[2]), "+f"(d[3])
        : "r"(a[0]), "r"(a[1]), "r"(a[2]), "r"(a[3]), "r"(b0), "r"(b1));
}

// ---------------------------------------------------------------------------
// GEMM: Y[M,512] = X[M,512] @ W[512,512]^T + bias (W row-major [out,in]).
// Tensor-core tf32. CTA tile 128x64, BK=32, 256 threads = 8 warps (4x2).
// Smem pad 36 (stride mod 32 == 4) => fragment LDS is conflict-free.
// ---------------------------------------------------------------------------
__global__ __launch_bounds__(256) void gemm_tc_kernel(
    const float* __restrict__ X, const float* __restrict__ W,
    const float* __restrict__ bias, float* __restrict__ Y)
{
    __shared__ float Xs[128][36];
    __shared__ float Ws[64][36];

    const int t      = threadIdx.x;
    const int lane   = t & 31;
    const int w      = t >> 5;
    const int warp_m = w >> 1;          // 0..3 -> 32 rows each
    const int warp_n = w & 1;           // 0..1 -> 32 cols each
    const int grp    = lane >> 2;       // 0..7
    const int tig    = lane & 3;        // 0..3
    const int m0     = blockIdx.y * 128;
    const int n0     = blockIdx.x * 64;

    float acc[2][4][4] = {};            // [mtile][ntile][frag]

    for (int k0 = 0; k0 < D_MODEL; k0 += 32) {
        // Fill Xs (128x32) and Ws (64x32), converting to tf32.
        #pragma unroll
        for (int rep = 0; rep < 4; rep++) {
            int idx = t + rep * 256;    // 0..1023
            int r = idx >> 3, c = idx & 7;
            float4 v = *(const float4*)(X + (size_t)(m0 + r) * D_MODEL + k0 + 4 * c);
            float4 o;
            o.x = f2tf32f(v.x); o.y = f2tf32f(v.y);
            o.z = f2tf32f(v.z); o.w = f2tf32f(v.w);
            *(float4*)&Xs[r][4 * c] = o;
        }
        #pragma unroll
        for (int rep = 0; rep < 2; rep++) {
            int idx = t + rep * 256;    // 0..511
            int r = idx >> 3, c = idx & 7;
            float4 v = *(const float4*)(W + (size_t)(n0 + r) * D_MODEL + k0 + 4 * c);
            float4 o;
            o.x = f2tf32f(v.x); o.y = f2tf32f(v.y);
            o.z = f2tf32f(v.z); o.w = f2tf32f(v.w);
            *(float4*)&Ws[r][4 * c] = o;
        }
        __syncthreads();

        #pragma unroll
        for (int ks = 0; ks < 4; ks++) {
            const int kk = ks * 8;
            uint32_t af[2][4];
            #pragma unroll
            for (int mt = 0; mt < 2; mt++) {
                int r = warp_m * 32 + mt * 16 + grp;
                af[mt][0] = __float_as_uint(Xs[r][kk + tig]);
                af[mt][1] = __float_as_uint(Xs[r + 8][kk + tig]);
                af[mt][2] = __float_as_uint(Xs[r][kk + tig + 4]);
                af[mt][3] = __float_as_uint(Xs[r + 8][kk + tig + 4]);
            }
            #pragma unroll
            for (int nt = 0; nt < 4; nt++) {
                int n = warp_n * 32 + nt * 8 + grp;
                uint32_t b0 = __float_as_uint(Ws[n][kk + tig]);
                uint32_t b1 = __float_as_uint(Ws[n][kk + tig + 4]);
                #pragma unroll
                for (int mt = 0; mt < 2; mt++)
                    mma_tf32(acc[mt][nt], af[mt], b0, b1);
            }
        }
        __syncthreads();
    }

    // Epilogue: + bias, write fp32
    #pragma unroll
    for (int mt = 0; mt < 2; mt++) {
        int r = m0 + warp_m * 32 + mt * 16 + grp;
        #pragma unroll
        for (int nt = 0; nt < 4; nt++) {
            int c = n0 + warp_n * 32 + nt * 8 + tig * 2;
            float b0 = bias[c], b1 = bias[c + 1];
            Y[(size_t)r * D_MODEL + c]           = acc[mt][nt][0] + b0;
            Y[(size_t)r * D_MODEL + c + 1]       = acc[mt][nt][1] + b1;
            Y[(size_t)(r + 8) * D_MODEL + c]     = acc[mt][nt][2] + b0;
            Y[(size_t)(r + 8) * D_MODEL + c + 1] = acc[mt][nt][3] + b1;
        }
    }
}

// ---------------------------------------------------------------------------
// Flash attention (tensor core). CTA = (b, h, 64-q-row tile). 256 thr, 8 warps.
// Warp tile: 16 q-rows (warp_m=w>>1) x 32 cols (warp_n=w&1).
// Q fragments in registers; K row-major and V transposed in smem (both are
// the `col` B operand). Parallel online softmax: 4 threads per row.
// ---------------------------------------------------------------------------
struct AttnSmem {
    float Ks[64][68];   // [kpos][d]   (tf32 bits)
    float Vt[64][68];   // [d][kpos]   (tf32 bits)
    float Ss[64][68];   // scores, then probabilities (tf32 bits)
    float gb[64];
    float mrow[64];
    float lrow[64];
    float cfac[64];
};
extern __shared__ unsigned char attn_smem_raw[];

__global__ __launch_bounds__(256) void attn_tc_kernel(
    const float* __restrict__ key_gate, const int* __restrict__ key_mask)
{
    AttnSmem& s = *reinterpret_cast<AttnSmem*>(attn_smem_raw);

    const int t      = threadIdx.x;
    const int lane   = t & 31;
    const int w      = t >> 5;
    const int warp_m = w >> 1;          // 0..3
    const int warp_n = w & 1;           // 0..1
    const int grp    = lane >> 2;
    const int tig    = lane & 3;
    const int q0     = blockIdx.x * 64;
    const int h      = blockIdx.y;
    const int b      = blockIdx.z;

    // --- Q fragments in registers (rows warp_m*16 .. +15, k = 0..63) ---
    const float* Qb = g_Qp + ((size_t)b * LQ + q0) * D_MODEL + h * D_HEAD;
    uint32_t qf[8][4];
    {
        const int r0 = warp_m * 16 + grp;
        #pragma unroll
        for (int ks = 0; ks < 8; ks++) {
            int kb = ks * 8;
            qf[ks][0] = f2tf32(Qb[(size_t)r0 * D_MODEL + kb + tig]);
            qf[ks][1] = f2tf32(Qb[(size_t)(r0 + 8) * D_MODEL + kb + tig]);
            qf[ks][2] = f2tf32(Qb[(size_t)r0 * D_MODEL + kb + tig + 4]);
            qf[ks][3] = f2tf32(Qb[(size_t)(r0 + 8) * D_MODEL + kb + tig + 4]);
        }
    }
    if (t < 64) { s.mrow[t] = -1e30f; s.lrow[t] = 0.0f; }

    float oacc[4][4] = {};
    const float scale = 0.125f;   // 1/sqrt(64)
    const int row  = t >> 2;      // softmax mapping: 4 threads / row
    const int part = t & 3;

    __syncthreads();

    for (int kt = 0; kt < LK / 64; kt++) {
        const int k0 = kt * 64;
        const float* Kb = g_Kp + ((size_t)b * LK + k0) * D_MODEL + h * D_HEAD;
        const float* Vb = g_Vp + ((size_t)b * LK + k0) * D_MODEL + h * D_HEAD;

        // Load K (row-major) and V (transposed), converting to tf32.
        #pragma unroll
        for (int rep = 0; rep < 4; rep++) {
            int idx = t + rep * 256;    // 0..1023
            int r = idx >> 4, c = idx & 15;
            float4 kv = *(const float4*)(Kb + (size_t)r * D_MODEL + 4 * c);
            float4 o;
            o.x = f2tf32f(kv.x); o.y = f2tf32f(kv.y);
            o.z = f2tf32f(kv.z); o.w = f2tf32f(kv.w);
            *(float4*)&s.Ks[r][4 * c] = o;
            float4 vv = *(const float4*)(Vb + (size_t)r * D_MODEL + 4 * c);
            s.Vt[4 * c + 0][r] = f2tf32f(vv.x);
            s.Vt[4 * c + 1][r] = f2tf32f(vv.y);
            s.Vt[4 * c + 2][r] = f2tf32f(vv.z);
            s.Vt[4 * c + 3][r] = f2tf32f(vv.w);
        }
        if (t < 64) {
            int k = k0 + t;
            float g = key_gate[(size_t)b * LK + k];
            s.gb[t] = (key_mask[(size_t)b * LK + k] == 0)
                          ? -1e30f : logf(fmaxf(g, 1e-6f));
        }
        __syncthreads();

        // ---- S = Q @ K^T (scaled) ----
        {
            float sacc[4][4] = {};
            #pragma unroll
            for (int ks = 0; ks < 8; ks++) {
                const int kk = ks * 8;
                #pragma unroll
                for (int nt = 0; nt < 4; nt++) {
                    int n = warp_n * 32 + nt * 8 + grp;
                    uint32_t b0 = __float_as_uint(s.Ks[n][kk + tig]);
                    uint32_t b1 = __float_as_uint(s.Ks[n][kk + tig + 4]);
                    mma_tf32(sacc[nt], qf[ks], b0, b1);
                }
            }
            const int r = warp_m * 16 + grp;
            #pragma unroll
            for (int nt = 0; nt < 4; nt++) {
                int c = warp_n * 32 + nt * 8 + tig * 2;
                s.Ss[r][c]         = sacc[nt][0] * scale;
                s.Ss[r][c + 1]     = sacc[nt][1] * scale;
                s.Ss[r + 8][c]     = sacc[nt][2] * scale;
                s.Ss[r + 8][c + 1] = sacc[nt][3] * scale;
            }
        }
        __syncthreads();

        // ---- online softmax: 4 threads per row, 16 cols each ----
        {
            float v[16];
            float mloc = -1e30f;
            #pragma unroll
            for (int i = 0; i < 4; i++) {
                float4 sv = *(float4*)&s.Ss[row][part * 16 + 4 * i];
                float4 gv = *(float4*)&s.gb[part * 16 + 4 * i];
                v[4*i+0] = sv.x + gv.x; v[4*i+1] = sv.y + gv.y;
                v[4*i+2] = sv.z + gv.z; v[4*i+3] = sv.w + gv.w;
                mloc = fmaxf(mloc, fmaxf(fmaxf(v[4*i], v[4*i+1]),
                                         fmaxf(v[4*i+2], v[4*i+3])));
            }
            mloc = fmaxf(mloc, __shfl_xor_sync(0xffffffff, mloc, 1));
            mloc = fmaxf(mloc, __shfl_xor_sync(0xffffffff, mloc, 2));
            float m_old = s.mrow[row];
            float m_new = fmaxf(m_old, mloc);

            float sum = 0.0f;
            #pragma unroll
            for (int i = 0; i < 4; i++) {
                float4 pv;
                float p0 = __expf(v[4*i+0] - m_new);
                float p1 = __expf(v[4*i+1] - m_new);
                float p2 = __expf(v[4*i+2] - m_new);
                float p3 = __expf(v[4*i+3] - m_new);
                sum += (p0 + p1) + (p2 + p3);
                pv.x = f2tf32f(p0); pv.y = f2tf32f(p1);
                pv.z = f2tf32f(p2); pv.w = f2tf32f(p3);
                *(float4*)&s.Ss[row][part * 16 + 4 * i] = pv;
            }
            sum += __shfl_xor_sync(0xffffffff, sum, 1);
            sum += __shfl_xor_sync(0xffffffff, sum, 2);
            if (part == 0) {
                float cf = __expf(m_old - m_new);
                s.cfac[row] = cf;
                s.lrow[row] = s.lrow[row] * cf + sum;
                s.mrow[row] = m_new;
            }
        }
        __syncthreads();

        // ---- O = O*cfac + P @ V ----
        {
            const int r = warp_m * 16 + grp;
            float cf0 = s.cfac[r], cf1 = s.cfac[r + 8];
            #pragma unroll
            for (int nt = 0; nt < 4; nt++) {
                oacc[nt][0] *= cf0; oacc[nt][1] *= cf0;
                oacc[nt][2] *= cf1; oacc[nt][3] *= cf1;
            }
            #pragma unroll
            for (int ks = 0; ks < 8; ks++) {
                const int kk = ks * 8;
                uint32_t af[4];
                af[0] = __float_as_uint(s.Ss[r][kk + tig]);
                af[1] = __float_as_uint(s.Ss[r + 8][kk + tig]);
                af[2] = __float_as_uint(s.Ss[r][kk + tig + 4]);
                af[3] = __float_as_uint(s.Ss[r + 8][kk + tig + 4]);
                #pragma unroll
                for (int nt = 0; nt < 4; nt++) {
                    int n = warp_n * 32 + nt * 8 + grp;
                    uint32_t b0 = __float_as_uint(s.Vt[n][kk + tig]);
                    uint32_t b1 = __float_as_uint(s.Vt[n][kk + tig + 4]);
                    mma_tf32(oacc[nt], af, b0, b1);
                }
            }
        }
        __syncthreads();
    }

    // ---- normalize + write ----
    {
        const int r = warp_m * 16 + grp;
        float l0 = 1.0f / s.lrow[r], l1 = 1.0f / s.lrow[r + 8];
        float* Ob = g_Att + ((size_t)b * LQ + q0) * D_MODEL + h * D_HEAD;
        #pragma unroll
        for (int nt = 0; nt < 4; nt++) {
            int c = warp_n * 32 + nt * 8 + tig * 2;
            Ob[(size_t)r * D_MODEL + c]           = oacc[nt][0] * l0;
            Ob[(size_t)r * D_MODEL + c + 1]       = oacc[nt][1] * l0;
            Ob[(size_t)(r + 8) * D_MODEL + c]     = oacc[nt][2] * l1;
            Ob[(size_t)(r + 8) * D_MODEL + c + 1] = oacc[nt][3] * l1;
        }
    }
}

// ---------------------------------------------------------------------------
// kernel_launch
// inputs: 0=q 1=kv 2=key_gate 3=key_mask 4=Wq 5=bq 6=Wk 7=bk 8=Wv 9=bv 10=Wo 11=bo
// ---------------------------------------------------------------------------
extern "C" void kernel_launch(void* const* d_in, const int* in_sizes, int n_in,
                              void* d_out, int out_size)
{
    (void)in_sizes; (void)n_in; (void)out_size;

    const float* q        = (const float*)d_in[0];
    const float* kv       = (const float*)d_in[1];
    const float* key_gate = (const float*)d_in[2];
    const int*   key_mask = (const int*)  d_in[3];
    const float* Wq = (const float*)d_in[4];
    const float* bq = (const float*)d_in[5];
    const float* Wk = (const float*)d_in[6];
    const float* bk = (const float*)d_in[7];
    const float* Wv = (const float*)d_in[8];
    const float* bv = (const float*)d_in[9];
    const float* Wo = (const float*)d_in[10];
    const float* bo = (const float*)d_in[11];
    float* out = (float*)d_out;

    float *pQp, *pKp, *pVp, *pAtt;
    cudaGetSymbolAddress((void**)&pQp,  g_Qp);
    cudaGetSymbolAddress((void**)&pKp,  g_Kp);
    cudaGetSymbolAddress((void**)&pVp,  g_Vp);
    cudaGetSymbolAddress((void**)&pAtt, g_Att);

    cudaFuncSetAttribute(attn_tc_kernel,
                         cudaFuncAttributeMaxDynamicSharedMemorySize,
                         (int)sizeof(AttnSmem));

    dim3 blk(256);
    // projections
    gemm_tc_kernel<<<dim3(8, (BATCH * LQ) / 128), blk>>>(q,  Wq, bq, pQp);
    gemm_tc_kernel<<<dim3(8, (BATCH * LK) / 128), blk>>>(kv, Wk, bk, pKp);
    gemm_tc_kernel<<<dim3(8, (BATCH * LK) / 128), blk>>>(kv, Wv, bv, pVp);
    // attention
    attn_tc_kernel<<<dim3(LQ / 64, NHEAD, BATCH), blk, sizeof(AttnSmem)>>>(
        key_gate, key_mask);
    // output projection
    gemm_tc_kernel<<<dim3(8, (BATCH * LQ) / 128), blk>>>(pAtt, Wo, bo, out);
}

// round 14
// speedup vs baseline: 1.6881x; 1.6838x over previous
#include <cuda_runtime.h>
#include <math.h>
#include <stdint.h>

#define D_MODEL 512
#define NHEAD   8
#define D_HEAD  64
#define BATCH   2
#define LQ      2048
#define LK      4096

// Scratch (static device globals — allocation-free)
__device__ float g_Qp [BATCH * LQ * D_MODEL];   // 8 MB  (tf32-rounded)
__device__ float g_Kp [BATCH * LK * D_MODEL];   // 16 MB (tf32-rounded)
__device__ float g_Vp [BATCH * LK * D_MODEL];   // 16 MB (tf32-rounded)
__device__ float g_Att[BATCH * LQ * D_MODEL];   // 8 MB
__device__ float g_gb [BATCH * LK];             // gate-log + mask bias

// ---------------------------------------------------------------------------
// helpers
// ---------------------------------------------------------------------------
__device__ __forceinline__ uint32_t f2tf32(float f) {
    uint32_t r;
    asm("cvt.rna.tf32.f32 %0, %1;" : "=r"(r) : "f"(f));
    return r;
}
__device__ __forceinline__ float f2tf32f(float f) {
    return __uint_as_float(f2tf32(f));
}

// D += A(16x8,row) * B(8x8,col), tf32 in, fp32 acc
__device__ __forceinline__ void mma_tf32(float* d, const uint32_t* a,
                                         uint32_t b0, uint32_t b1) {
    asm volatile(
        "mma.sync.aligned.m16n8k8.row.col.f32.tf32.tf32.f32 "
        "{%0,%1,%2,%3},{%4,%5,%6,%7},{%8,%9},{%0,%1,%2,%3};"
        : "+f"(d[0]), "+f"(d[1]), "+f"(d[2]), "+f"(d[3])
        : "r"(a[0]), "r"(a[1]), "r"(a[2]), "r"(a[3]), "r"(b0), "r"(b1));
}

__device__ __forceinline__ uint32_t sm_u32(const void* p) {
    return (uint32_t)__cvta_generic_to_shared(p);
}
__device__ __forceinline__ void cpa16(uint32_t dst, const void* src) {
    asm volatile("cp.async.cg.shared.global [%0], [%1], 16;" :: "r"(dst), "l"(src));
}
__device__ __forceinline__ void cpa4(uint32_t dst, const void* src) {
    asm volatile("cp.async.ca.shared.global [%0], [%1], 4;" :: "r"(dst), "l"(src));
}
__device__ __forceinline__ void cpa_commit() {
    asm volatile("cp.async.commit_group;");
}
__device__ __forceinline__ void cpa_wait_all() {
    asm volatile("cp.async.wait_group 0;");
}

// ---------------------------------------------------------------------------
// gate bias precompute: g_gb = mask ? log(max(gate,1e-6)) : -1e30
// ---------------------------------------------------------------------------
__global__ void gb_kernel(const float* __restrict__ gate,
                          const int* __restrict__ mask, float* __restrict__ out)
{
    int i = blockIdx.x * 256 + threadIdx.x;
    if (i < BATCH * LK)
        out[i] = mask[i] ? logf(fmaxf(gate[i], 1e-6f)) : -1e30f;
}

// ---------------------------------------------------------------------------
// GEMM: Y[M,512] = X[M,512] @ W[512,512]^T + bias (W row-major [out,in]).
// Tensor-core tf32. CTA tile 128x64, BK=32, 256 threads = 8 warps (4x2).
// ROUND_TF32: round the output to tf32 (for Q/K/V projections feeding attn).
// ---------------------------------------------------------------------------
template <bool ROUND_TF32>
__global__ __launch_bounds__(256) void gemm_tc_kernel(
    const float* __restrict__ X, const float* __restrict__ W,
    const float* __restrict__ bias, float* __restrict__ Y)
{
    __shared__ float Xs[128][36];
    __shared__ float Ws[64][36];

    const int t      = threadIdx.x;
    const int lane   = t & 31;
    const int w      = t >> 5;
    const int warp_m = w >> 1;
    const int warp_n = w & 1;
    const int grp    = lane >> 2;
    const int tig    = lane & 3;
    const int m0     = blockIdx.y * 128;
    const int n0     = blockIdx.x * 64;

    float acc[2][4][4] = {};

    for (int k0 = 0; k0 < D_MODEL; k0 += 32) {
        #pragma unroll
        for (int rep = 0; rep < 4; rep++) {
            int idx = t + rep * 256;
            int r = idx >> 3, c = idx & 7;
            float4 v = *(const float4*)(X + (size_t)(m0 + r) * D_MODEL + k0 + 4 * c);
            float4 o;
            o.x = f2tf32f(v.x); o.y = f2tf32f(v.y);
            o.z = f2tf32f(v.z); o.w = f2tf32f(v.w);
            *(float4*)&Xs[r][4 * c] = o;
        }
        #pragma unroll
        for (int rep = 0; rep < 2; rep++) {
            int idx = t + rep * 256;
            int r = idx >> 3, c = idx & 7;
            float4 v = *(const float4*)(W + (size_t)(n0 + r) * D_MODEL + k0 + 4 * c);
            float4 o;
            o.x = f2tf32f(v.x); o.y = f2tf32f(v.y);
            o.z = f2tf32f(v.z); o.w = f2tf32f(v.w);
            *(float4*)&Ws[r][4 * c] = o;
        }
        __syncthreads();

        #pragma unroll
        for (int ks = 0; ks < 4; ks++) {
            const int kk = ks * 8;
            uint32_t af[2][4];
            #pragma unroll
            for (int mt = 0; mt < 2; mt++) {
                int r = warp_m * 32 + mt * 16 + grp;
                af[mt][0] = __float_as_uint(Xs[r][kk + tig]);
                af[mt][1] = __float_as_uint(Xs[r + 8][kk + tig]);
                af[mt][2] = __float_as_uint(Xs[r][kk + tig + 4]);
                af[mt][3] = __float_as_uint(Xs[r + 8][kk + tig + 4]);
            }
            #pragma unroll
            for (int nt = 0; nt < 4; nt++) {
                int n = warp_n * 32 + nt * 8 + grp;
                uint32_t b0 = __float_as_uint(Ws[n][kk + tig]);
                uint32_t b1 = __float_as_uint(Ws[n][kk + tig + 4]);
                #pragma unroll
                for (int mt = 0; mt < 2; mt++)
                    mma_tf32(acc[mt][nt], af[mt], b0, b1);
            }
        }
        __syncthreads();
    }

    #pragma unroll
    for (int mt = 0; mt < 2; mt++) {
        int r = m0 + warp_m * 32 + mt * 16 + grp;
        #pragma unroll
        for (int nt = 0; nt < 4; nt++) {
            int c = n0 + warp_n * 32 + nt * 8 + tig * 2;
            float b0 = bias[c], b1 = bias[c + 1];
            float v00 = acc[mt][nt][0] + b0, v01 = acc[mt][nt][1] + b1;
            float v10 = acc[mt][nt][2] + b0, v11 = acc[mt][nt][3] + b1;
            if (ROUND_TF32) {
                v00 = f2tf32f(v00); v01 = f2tf32f(v01);
                v10 = f2tf32f(v10); v11 = f2tf32f(v11);
            }
            Y[(size_t)r * D_MODEL + c]           = v00;
            Y[(size_t)r * D_MODEL + c + 1]       = v01;
            Y[(size_t)(r + 8) * D_MODEL + c]     = v10;
            Y[(size_t)(r + 8) * D_MODEL + c + 1] = v11;
        }
    }
}

// ---------------------------------------------------------------------------
// Flash attention v2: CTA = (b, h, 64-q-row tile). 128 threads = 4 warps.
// Each warp owns 16 q-rows x full 64-key width. Softmax stats entirely in
// registers (quad shuffles). P stays in registers (C->A fragment shuffle).
// K/V double-buffered via cp.async: ONE __syncthreads per key tile.
// ---------------------------------------------------------------------------
struct AttnSmem {
    float Ks[2][64][68];   // [buf][key][dim]  stride 68: S-mma LDS conflict-free
    float Vs[2][64][72];   // [buf][key][dim]  stride 72: PV-mma LDS conflict-free
    float gbs[2][64];
};
extern __shared__ unsigned char attn_smem_raw[];

__global__ __launch_bounds__(128) void attn_tc2_kernel()
{
    AttnSmem& s = *reinterpret_cast<AttnSmem*>(attn_smem_raw);

    const int t    = threadIdx.x;
    const int lane = t & 31;
    const int w    = t >> 5;          // 0..3: q-row group
    const int grp  = lane >> 2;       // 0..7
    const int tig  = lane & 3;        // 0..3
    const int q0   = blockIdx.x * 64;
    const int h    = blockIdx.y;
    const int b    = blockIdx.z;

    const float* Qb  = g_Qp + ((size_t)b * LQ + q0) * D_MODEL + h * D_HEAD;
    const float* Kb0 = g_Kp + ((size_t)b * LK) * D_MODEL + h * D_HEAD;
    const float* Vb0 = g_Vp + ((size_t)b * LK) * D_MODEL + h * D_HEAD;
    const float* gbp = g_gb + (size_t)b * LK;

    // ---- prologue: start tile 0 cp.async into buf 0 ----
    {
        uint32_t ksb = sm_u32(&s.Ks[0][0][0]);
        uint32_t vsb = sm_u32(&s.Vs[0][0][0]);
        #pragma unroll
        for (int rep = 0; rep < 8; rep++) {
            int idx = t + rep * 128;
            int r = idx >> 4, c = idx & 15;
            cpa16(ksb + (r * 68 + 4 * c) * 4, Kb0 + (size_t)r * D_MODEL + 4 * c);
            cpa16(vsb + (r * 72 + 4 * c) * 4, Vb0 + (size_t)r * D_MODEL + 4 * c);
        }
        if (t < 64) cpa4(sm_u32(&s.gbs[0][t]), gbp + t);
        cpa_commit();
    }

    // ---- stage Q (scaled by 1/8, exact on tf32 bits) into Ks[1] ----
    #pragma unroll
    for (int rep = 0; rep < 8; rep++) {
        int idx = t + rep * 128;
        int r = idx >> 4, c = idx & 15;
        float4 v = *(const float4*)(Qb + (size_t)r * D_MODEL + 4 * c);
        v.x *= 0.125f; v.y *= 0.125f; v.z *= 0.125f; v.w *= 0.125f;
        *(float4*)&s.Ks[1][r][4 * c] = v;
    }
    __syncthreads();

    uint32_t qf[8][4];
    {
        const int r0 = w * 16 + grp;
        #pragma unroll
        for (int ks = 0; ks < 8; ks++) {
            int kk = ks * 8;
            qf[ks][0] = __float_as_uint(s.Ks[1][r0][kk + tig]);
            qf[ks][1] = __float_as_uint(s.Ks[1][r0 + 8][kk + tig]);
            qf[ks][2] = __float_as_uint(s.Ks[1][r0][kk + tig + 4]);
            qf[ks][3] = __float_as_uint(s.Ks[1][r0 + 8][kk + tig + 4]);
        }
    }
    cpa_wait_all();
    __syncthreads();   // qf reads done (buf1 free), tile0 visible

    float oacc[8][4] = {};
    float mrow0 = -1e30f, mrow1 = -1e30f;
    float lrow0 = 0.0f,   lrow1 = 0.0f;
    const int src0 = (lane & ~3) | (tig >> 1);   // quad lane holding col tig
    const int src1 = src0 + 2;                   // quad lane holding col tig+4
    const bool odd = (tig & 1);

    for (int kt = 0; kt < LK / 64; kt++) {
        const int cur = kt & 1;

        // prefetch next tile into the other buffer
        if (kt + 1 < LK / 64) {
            const int nxt = cur ^ 1;
            const float* Kb = Kb0 + (size_t)(kt + 1) * 64 * D_MODEL;
            const float* Vb = Vb0 + (size_t)(kt + 1) * 64 * D_MODEL;
            uint32_t ksb = sm_u32(&s.Ks[nxt][0][0]);
            uint32_t vsb = sm_u32(&s.Vs[nxt][0][0]);
            #pragma unroll
            for (int rep = 0; rep < 8; rep++) {
                int idx = t + rep * 128;
                int r = idx >> 4, c = idx & 15;
                cpa16(ksb + (r * 68 + 4 * c) * 4, Kb + (size_t)r * D_MODEL + 4 * c);
                cpa16(vsb + (r * 72 + 4 * c) * 4, Vb + (size_t)r * D_MODEL + 4 * c);
            }
            if (t < 64) cpa4(sm_u32(&s.gbs[nxt][t]), gbp + (kt + 1) * 64 + t);
            cpa_commit();
        }

        // ---- S = Qscaled @ K^T ----
        float sacc[8][4] = {};
        #pragma unroll
        for (int ks = 0; ks < 8; ks++) {
            const int kk = ks * 8;
            #pragma unroll
            for (int nt = 0; nt < 8; nt++) {
                int n = nt * 8 + grp;
                uint32_t b0 = __float_as_uint(s.Ks[cur][n][kk + tig]);
                uint32_t b1 = __float_as_uint(s.Ks[cur][n][kk + tig + 4]);
                mma_tf32(sacc[nt], qf[ks], b0, b1);
            }
        }

        // ---- + gate bias, row max (registers + quad shuffles) ----
        float m0 = -1e30f, m1 = -1e30f;
        #pragma unroll
        for (int nt = 0; nt < 8; nt++) {
            float2 g2 = *(const float2*)&s.gbs[cur][nt * 8 + 2 * tig];
            sacc[nt][0] += g2.x; sacc[nt][1] += g2.y;
            sacc[nt][2] += g2.x; sacc[nt][3] += g2.y;
            m0 = fmaxf(m0, fmaxf(sacc[nt][0], sacc[nt][1]));
            m1 = fmaxf(m1, fmaxf(sacc[nt][2], sacc[nt][3]));
        }
        m0 = fmaxf(m0, __shfl_xor_sync(0xffffffff, m0, 1));
        m0 = fmaxf(m0, __shfl_xor_sync(0xffffffff, m0, 2));
        m1 = fmaxf(m1, __shfl_xor_sync(0xffffffff, m1, 1));
        m1 = fmaxf(m1, __shfl_xor_sync(0xffffffff, m1, 2));

        float mn0 = fmaxf(mrow0, m0), mn1 = fmaxf(mrow1, m1);
        float cf0 = __expf(mrow0 - mn0), cf1 = __expf(mrow1 - mn1);
        mrow0 = mn0; mrow1 = mn1;

        // ---- exp (P overwrites sacc, stored as tf32 bits) ----
        float s0 = 0.0f, s1 = 0.0f;
        #pragma unroll
        for (int nt = 0; nt < 8; nt++) {
            float p0 = __expf(sacc[nt][0] - mn0);
            float p1 = __expf(sacc[nt][1] - mn0);
            float p2 = __expf(sacc[nt][2] - mn1);
            float p3 = __expf(sacc[nt][3] - mn1);
            s0 += p0 + p1; s1 += p2 + p3;
            sacc[nt][0] = f2tf32f(p0); sacc[nt][1] = f2tf32f(p1);
            sacc[nt][2] = f2tf32f(p2); sacc[nt][3] = f2tf32f(p3);
        }
        s0 += __shfl_xor_sync(0xffffffff, s0, 1);
        s0 += __shfl_xor_sync(0xffffffff, s0, 2);
        s1 += __shfl_xor_sync(0xffffffff, s1, 1);
        s1 += __shfl_xor_sync(0xffffffff, s1, 2);
        lrow0 = lrow0 * cf0 + s0;
        lrow1 = lrow1 * cf1 + s1;

        // ---- rescale O, then O += P @ V ----
        #pragma unroll
        for (int mt = 0; mt < 8; mt++) {
            oacc[mt][0] *= cf0; oacc[mt][1] *= cf0;
            oacc[mt][2] *= cf1; oacc[mt][3] *= cf1;
        }
        #pragma unroll
        for (int kb = 0; kb < 8; kb++) {
            // C-layout (cols 2tig,2tig+1) -> A-layout (cols tig, tig+4)
            float x0 = __shfl_sync(0xffffffff, sacc[kb][0], src0);
            float y0 = __shfl_sync(0xffffffff, sacc[kb][1], src0);
            float x1 = __shfl_sync(0xffffffff, sacc[kb][2], src0);
            float y1 = __shfl_sync(0xffffffff, sacc[kb][3], src0);
            float x2 = __shfl_sync(0xffffffff, sacc[kb][0], src1);
            float y2 = __shfl_sync(0xffffffff, sacc[kb][1], src1);
            float x3 = __shfl_sync(0xffffffff, sacc[kb][2], src1);
            float y3 = __shfl_sync(0xffffffff, sacc[kb][3], src1);
            uint32_t a[4];
            a[0] = __float_as_uint(odd ? y0 : x0);
            a[1] = __float_as_uint(odd ? y1 : x1);
            a[2] = __float_as_uint(odd ? y2 : x2);
            a[3] = __float_as_uint(odd ? y3 : x3);
            const int k = kb * 8;
            #pragma unroll
            for (int mt = 0; mt < 8; mt++) {
                int n = mt * 8 + grp;
                uint32_t b0 = __float_as_uint(s.Vs[cur][k + tig][n]);
                uint32_t b1 = __float_as_uint(s.Vs[cur][k + tig + 4][n]);
                mma_tf32(oacc[mt], a, b0, b1);
            }
        }

        cpa_wait_all();
        __syncthreads();   // next buffer filled; this buffer's reads done
    }

    // ---- normalize + write ----
    {
        float il0 = 1.0f / lrow0, il1 = 1.0f / lrow1;
        const int r = w * 16 + grp;
        float* Ob = g_Att + ((size_t)b * LQ + q0) * D_MODEL + h * D_HEAD;
        #pragma unroll
        for (int mt = 0; mt < 8; mt++) {
            int c = mt * 8 + 2 * tig;
            float2 v0 = { oacc[mt][0] * il0, oacc[mt][1] * il0 };
            float2 v1 = { oacc[mt][2] * il1, oacc[mt][3] * il1 };
            *(float2*)(Ob + (size_t)r * D_MODEL + c)       = v0;
            *(float2*)(Ob + (size_t)(r + 8) * D_MODEL + c) = v1;
        }
    }
}

// ---------------------------------------------------------------------------
// kernel_launch
// inputs: 0=q 1=kv 2=key_gate 3=key_mask 4=Wq 5=bq 6=Wk 7=bk 8=Wv 9=bv 10=Wo 11=bo
// ---------------------------------------------------------------------------
extern "C" void kernel_launch(void* const* d_in, const int* in_sizes, int n_in,
                              void* d_out, int out_size)
{
    (void)in_sizes; (void)n_in; (void)out_size;

    const float* q        = (const float*)d_in[0];
    const float* kv       = (const float*)d_in[1];
    const float* key_gate = (const float*)d_in[2];
    const int*   key_mask = (const int*)  d_in[3];
    const float* Wq = (const float*)d_in[4];
    const float* bq = (const float*)d_in[5];
    const float* Wk = (const float*)d_in[6];
    const float* bk = (const float*)d_in[7];
    const float* Wv = (const float*)d_in[8];
    const float* bv = (const float*)d_in[9];
    const float* Wo = (const float*)d_in[10];
    const float* bo = (const float*)d_in[11];
    float* out = (float*)d_out;

    float *pQp, *pKp, *pVp, *pAtt, *pGb;
    cudaGetSymbolAddress((void**)&pQp,  g_Qp);
    cudaGetSymbolAddress((void**)&pKp,  g_Kp);
    cudaGetSymbolAddress((void**)&pVp,  g_Vp);
    cudaGetSymbolAddress((void**)&pAtt, g_Att);
    cudaGetSymbolAddress((void**)&pGb,  g_gb);

    cudaFuncSetAttribute(attn_tc2_kernel,
                         cudaFuncAttributeMaxDynamicSharedMemorySize,
                         (int)sizeof(AttnSmem));

    dim3 blk(256);
    // gate bias precompute
    gb_kernel<<<(BATCH * LK + 255) / 256, 256>>>(key_gate, key_mask, pGb);
    // projections (outputs rounded to tf32 for attention)
    gemm_tc_kernel<true><<<dim3(8, (BATCH * LQ) / 128), blk>>>(q,  Wq, bq, pQp);
    gemm_tc_kernel<true><<<dim3(8, (BATCH * LK) / 128), blk>>>(kv, Wk, bk, pKp);
    gemm_tc_kernel<true><<<dim3(8, (BATCH * LK) / 128), blk>>>(kv, Wv, bv, pVp);
    // attention
    attn_tc2_kernel<<<dim3(LQ / 64, NHEAD, BATCH), dim3(128),
                      sizeof(AttnSmem)>>>();
    // output projection (full fp32 output)
    gemm_tc_kernel<false><<<dim3(8, (BATCH * LQ) / 128), blk>>>(pAtt, Wo, bo, out);
}